// round 2
// baseline (speedup 1.0000x reference)
#include <cuda_runtime.h>

#define MAX_NODES 100000
#define MAX_EDGES 3200000

// ---------------- scratch (device globals; no allocation allowed) ------------
__device__ int   g_is32;
__device__ int   g_cnt[MAX_NODES];
__device__ int   g_rowptr[MAX_NODES + 1];
__device__ int   g_cursor[MAX_NODES];
__device__ float g_dinv[MAX_NODES];
__device__ int   g_src[MAX_EDGES];
__device__ int   g_dst[MAX_EDGES];
__device__ int   g_col[MAX_EDGES];
__device__ float g_bufA[(size_t)MAX_NODES * 64];
__device__ float g_bufB[(size_t)MAX_NODES * 64];

// ---------------- dtype detection + CSR construction -------------------------
// If edge_index is true int64, every value < 2^32 so high words are all zero.
// If it is int32 (JAX x64-disabled default), packed pairs make high half
// nonzero with overwhelming probability across 64 samples.
__global__ void detect_dtype_kernel(const unsigned long long* __restrict__ ei) {
    if (threadIdx.x == 0 && blockIdx.x == 0) {
        int is32 = 0;
        for (int i = 0; i < 64; i++)
            if (ei[i] >> 32) is32 = 1;
        g_is32 = is32;
    }
}

__global__ void zero_cnt_kernel(int n) {
    int i = blockIdx.x * blockDim.x + threadIdx.x;
    if (i < n) g_cnt[i] = 0;
}

__global__ void count_convert_kernel(const void* __restrict__ eiv, int E, int N) {
    int i = blockIdx.x * blockDim.x + threadIdx.x;
    if (i >= E) return;
    int s, d;
    if (g_is32) {
        const int* e = (const int*)eiv;
        s = e[i];
        d = e[E + i];
    } else {
        const long long* e = (const long long*)eiv;
        s = (int)e[i];
        d = (int)e[E + i];
    }
    // safety clamp: never index OOB even if detection were wrong
    if ((unsigned)s >= (unsigned)N) s = 0;
    if ((unsigned)d >= (unsigned)N) d = 0;
    g_src[i] = s;
    g_dst[i] = d;
    atomicAdd(&g_cnt[d], 1);
}

// Single-block multi-chunk exclusive scan of g_cnt -> g_rowptr/g_cursor,
// plus dinv = rsqrt(deg+1) (self-loop included, matching reference).
__global__ void scan_build_kernel(int N) {
    __shared__ int s[1024];
    __shared__ int run;
    int t = threadIdx.x;
    if (t == 0) run = 0;
    __syncthreads();
    int nch = (N + 1023) >> 10;
    for (int c = 0; c < nch; c++) {
        int idx = (c << 10) + t;
        int v = (idx < N) ? g_cnt[idx] : 0;
        s[t] = v;
        __syncthreads();
        for (int off = 1; off < 1024; off <<= 1) {
            int tmp = (t >= off) ? s[t - off] : 0;
            __syncthreads();
            s[t] += tmp;
            __syncthreads();
        }
        int excl = s[t] - v + run;
        if (idx < N) {
            g_rowptr[idx] = excl;
            g_cursor[idx] = excl;
            g_dinv[idx]   = rsqrtf((float)(v + 1));
        }
        __syncthreads();
        if (t == 0) run += s[1023];
        __syncthreads();
    }
    if (t == 0) g_rowptr[N] = run;
}

__global__ void fill_col_kernel(int E) {
    int i = blockIdx.x * blockDim.x + threadIdx.x;
    if (i < E) {
        int d = g_dst[i];
        int p = atomicAdd(&g_cursor[d], 1);
        g_col[p] = g_src[i];
    }
}

// ---------------- dense GEMM: Y[N,64] = X[N,K] @ W[K,64] (fp32, f32x2 FMA) ---
__device__ __forceinline__ void ffma2(unsigned long long& acc,
                                      unsigned long long a,
                                      unsigned long long b) {
    asm("fma.rn.f32x2 %0, %1, %2, %0;" : "+l"(acc) : "l"(a), "l"(b));
}

template <int K>
__global__ void __launch_bounds__(128) gemm64_kernel(
    const float* __restrict__ X, const float* __restrict__ W,
    float* __restrict__ Y, int N) {
    constexpr int KP = K + 4;  // pad to dodge smem bank conflicts on x reads
    extern __shared__ __align__(16) float smem[];
    float* sW = smem;            // [K][64]
    float* sX = smem + K * 64;   // [64][KP]

    int t = threadIdx.x;
    int node0 = blockIdx.x * 64;

    for (int i = t; i < K * 16; i += 128)
        ((float4*)sW)[i] = ((const float4*)W)[i];

    constexpr int RQ = K / 4;
    for (int i = t; i < 64 * RQ; i += 128) {
        int r = i / RQ, c = i % RQ;
        float4 v = make_float4(0.f, 0.f, 0.f, 0.f);
        if (node0 + r < N) v = *(const float4*)&X[(size_t)(node0 + r) * K + 4 * c];
        *(float4*)&sX[r * KP + 4 * c] = v;
    }
    __syncthreads();

    int tx = t & 7;    // 8 groups of 8 output cols
    int ty = t >> 3;   // 16 groups of 4 nodes
    unsigned long long acc[4][4];
#pragma unroll
    for (int i = 0; i < 4; i++)
#pragma unroll
        for (int j = 0; j < 4; j++) acc[i][j] = 0ull;

#pragma unroll 4
    for (int k = 0; k < K; k++) {
        ulonglong2 w0 = *(const ulonglong2*)&sW[k * 64 + 8 * tx];
        ulonglong2 w1 = *(const ulonglong2*)&sW[k * 64 + 8 * tx + 4];
#pragma unroll
        for (int i = 0; i < 4; i++) {
            float xv = sX[(4 * ty + i) * KP + k];
            unsigned long long xx;
            asm("mov.b64 %0, {%1, %1};" : "=l"(xx) : "f"(xv));
            ffma2(acc[i][0], w0.x, xx);
            ffma2(acc[i][1], w0.y, xx);
            ffma2(acc[i][2], w1.x, xx);
            ffma2(acc[i][3], w1.y, xx);
        }
    }

#pragma unroll
    for (int i = 0; i < 4; i++) {
        int node = node0 + 4 * ty + i;
        if (node < N) {
            *(ulonglong2*)&Y[(size_t)node * 64 + 8 * tx] =
                make_ulonglong2(acc[i][0], acc[i][1]);
            *(ulonglong2*)&Y[(size_t)node * 64 + 8 * tx + 4] =
                make_ulonglong2(acc[i][2], acc[i][3]);
        }
    }
}

// ---------------- sparse aggregation: warp per dst node ----------------------
// out[d] = dinv[d] * sum_{src in row(d)} dinv[src]*H[src] + dinv[d]^2*H[d] + b
__global__ void __launch_bounds__(256) agg_kernel(
    const float* __restrict__ H, const float* __restrict__ bias,
    float* __restrict__ OUT, int N, int do_relu) {
    int gw = (blockIdx.x * blockDim.x + threadIdx.x) >> 5;
    if (gw >= N) return;
    int lane = threadIdx.x & 31;

    int rs = g_rowptr[gw], re = g_rowptr[gw + 1];
    float ax = 0.f, ay = 0.f;

    int base = rs;
    for (; base + 32 <= re; base += 32) {
        int sidx = g_col[base + lane];
#pragma unroll 8
        for (int i = 0; i < 32; i++) {
            int src = __shfl_sync(0xffffffffu, sidx, i);
            float w = g_dinv[src];
            float2 hv = *(const float2*)&H[(size_t)src * 64 + 2 * lane];
            ax = fmaf(w, hv.x, ax);
            ay = fmaf(w, hv.y, ay);
        }
    }
    int rem = re - base;
    if (rem > 0) {
        int sidx = (lane < rem) ? g_col[base + lane] : 0;
        for (int i = 0; i < rem; i++) {
            int src = __shfl_sync(0xffffffffu, sidx, i);
            float w = g_dinv[src];
            float2 hv = *(const float2*)&H[(size_t)src * 64 + 2 * lane];
            ax = fmaf(w, hv.x, ax);
            ay = fmaf(w, hv.y, ay);
        }
    }

    float wd = g_dinv[gw];
    float2 hs = *(const float2*)&H[(size_t)gw * 64 + 2 * lane];
    float2 bv = *(const float2*)&bias[2 * lane];
    float ox = fmaf(wd, ax, wd * wd * hs.x) + bv.x;
    float oy = fmaf(wd, ay, wd * wd * hs.y) + bv.y;
    if (do_relu) {
        ox = fmaxf(ox, 0.f);
        oy = fmaxf(oy, 0.f);
    }
    float2 o;
    o.x = ox;
    o.y = oy;
    *(float2*)&OUT[(size_t)gw * 64 + 2 * lane] = o;
}

// ---------------- launch ------------------------------------------------------
extern "C" void kernel_launch(void* const* d_in, const int* in_sizes, int n_in,
                              void* d_out, int out_size) {
    const float* x   = (const float*)d_in[0];
    const void*  ei  = d_in[1];
    const float* W1  = (const float*)d_in[2];
    const float* b1  = (const float*)d_in[3];
    const float* W2  = (const float*)d_in[4];
    const float* b2  = (const float*)d_in[5];
    float*       out = (float*)d_out;

    int N = in_sizes[0] / 128;   // 100000
    int E = in_sizes[1] / 2;     // 3200000

    void *pA = nullptr, *pB = nullptr;
    cudaGetSymbolAddress(&pA, g_bufA);
    cudaGetSymbolAddress(&pB, g_bufB);
    float* bufA = (float*)pA;
    float* bufB = (float*)pB;

    int smem1 = (128 * 64 + 64 * (128 + 4)) * 4;
    int smem2 = (64 * 64 + 64 * (64 + 4)) * 4;
    cudaFuncSetAttribute(gemm64_kernel<128>,
                         cudaFuncAttributeMaxDynamicSharedMemorySize, smem1);
    cudaFuncSetAttribute(gemm64_kernel<64>,
                         cudaFuncAttributeMaxDynamicSharedMemorySize, smem2);

    // --- build CSR (dst-grouped) ---
    detect_dtype_kernel<<<1, 32>>>((const unsigned long long*)ei);
    zero_cnt_kernel<<<(N + 255) / 256, 256>>>(N);
    count_convert_kernel<<<(E + 255) / 256, 256>>>(ei, E, N);
    scan_build_kernel<<<1, 1024>>>(N);
    fill_col_kernel<<<(E + 255) / 256, 256>>>(E);

    // --- layer 1: t = x@W1 ; h = relu(A_norm t + b1) ---
    gemm64_kernel<128><<<(N + 63) / 64, 128, smem1>>>(x, W1, bufA, N);
    agg_kernel<<<(N + 7) / 8, 256>>>(bufA, b1, bufB, N, 1);

    // --- layer 2: t = h@W2 ; out = A_norm t + b2 ---
    gemm64_kernel<64><<<(N + 63) / 64, 128, smem2>>>(bufB, W2, bufA, N);
    agg_kernel<<<(N + 7) / 8, 256>>>(bufA, b2, out, N, 0);
}

// round 3
// speedup vs baseline: 1.4908x; 1.4908x over previous
#include <cuda_runtime.h>

#define MAX_NODES 100000
#define MAX_EDGES 3200000

// ---------------- scratch (device globals; no allocation allowed) ------------
__device__ int   g_is32;
__device__ int   g_cnt[MAX_NODES];
__device__ int   g_rowptr[MAX_NODES + 1];
__device__ int   g_cursor[MAX_NODES];
__device__ float g_dinv[MAX_NODES];
__device__ int   g_src[MAX_EDGES];
__device__ int   g_dst[MAX_EDGES];
__device__ int   g_col[MAX_EDGES];
__device__ int   g_bsum[128];
__device__ int   g_boff[128];
__device__ float g_bufA[(size_t)MAX_NODES * 64];
__device__ float g_bufB[(size_t)MAX_NODES * 64];

// ---------------- dtype detection -------------------------------------------
// Reference asks for int64 edge_index, but JAX x64-off silently yields int32.
// True int64 values < 2^32 => high words all zero; int32 packing makes the
// high half nonzero w.h.p. across 64 samples.
__global__ void detect_dtype_kernel(const unsigned long long* __restrict__ ei) {
    if (threadIdx.x == 0 && blockIdx.x == 0) {
        int is32 = 0;
        for (int i = 0; i < 64; i++)
            if (ei[i] >> 32) is32 = 1;
        g_is32 = is32;
    }
}

__global__ void zero_cnt_kernel(int n) {
    int i = blockIdx.x * blockDim.x + threadIdx.x;
    if (i < n) g_cnt[i] = 0;
}

__global__ void count_convert_kernel(const void* __restrict__ eiv, int E, int N) {
    int i = blockIdx.x * blockDim.x + threadIdx.x;
    if (i >= E) return;
    int s, d;
    if (g_is32) {
        const int* e = (const int*)eiv;
        s = e[i];
        d = e[E + i];
    } else {
        const long long* e = (const long long*)eiv;
        s = (int)e[i];
        d = (int)e[E + i];
    }
    if ((unsigned)s >= (unsigned)N) s = 0;
    if ((unsigned)d >= (unsigned)N) d = 0;
    g_src[i] = s;
    g_dst[i] = d;
    atomicAdd(&g_cnt[d], 1);
}

// ---------------- hierarchical exclusive scan of g_cnt ----------------------
// Phase 1: block-local exclusive scan (1024/block), block sums out.
__global__ void __launch_bounds__(1024) scan1_kernel(int N) {
    __shared__ int wsum[32];
    int t = threadIdx.x;
    int lane = t & 31, wid = t >> 5;
    int idx = blockIdx.x * 1024 + t;
    int v = (idx < N) ? g_cnt[idx] : 0;

    int x = v;
#pragma unroll
    for (int off = 1; off < 32; off <<= 1) {
        int y = __shfl_up_sync(0xffffffffu, x, off);
        if (lane >= off) x += y;
    }
    if (lane == 31) wsum[wid] = x;
    __syncthreads();
    if (wid == 0) {
        int w = wsum[lane];
#pragma unroll
        for (int off = 1; off < 32; off <<= 1) {
            int y = __shfl_up_sync(0xffffffffu, w, off);
            if (lane >= off) w += y;
        }
        wsum[lane] = w;
    }
    __syncthreads();
    int base = (wid > 0) ? wsum[wid - 1] : 0;
    int incl = x + base;
    if (idx < N) g_rowptr[idx] = incl - v;  // block-local exclusive
    if (t == 1023) g_bsum[blockIdx.x] = incl;
}

// Phase 2: scan the (<=128) block sums in one block.
__global__ void __launch_bounds__(128) scan2_kernel(int nb) {
    __shared__ int wsum[4];
    int t = threadIdx.x;
    int lane = t & 31, wid = t >> 5;
    int v = (t < nb) ? g_bsum[t] : 0;
    int x = v;
#pragma unroll
    for (int off = 1; off < 32; off <<= 1) {
        int y = __shfl_up_sync(0xffffffffu, x, off);
        if (lane >= off) x += y;
    }
    if (lane == 31) wsum[wid] = x;
    __syncthreads();
    int add = 0;
    for (int w = 0; w < wid; w++) add += wsum[w];
    if (t < nb) g_boff[t] = x + add - v;  // exclusive
}

// Phase 3: add block offsets; emit rowptr/cursor/dinv.
__global__ void scan3_kernel(int N, int E) {
    int idx = blockIdx.x * blockDim.x + threadIdx.x;
    if (idx < N) {
        int excl = g_rowptr[idx] + g_boff[idx >> 10];
        g_rowptr[idx] = excl;
        g_cursor[idx] = excl;
        g_dinv[idx]   = rsqrtf((float)(g_cnt[idx] + 1));
    }
    if (idx == 0) g_rowptr[N] = E;
}

__global__ void fill_col_kernel(int E) {
    int i = blockIdx.x * blockDim.x + threadIdx.x;
    if (i < E) {
        int d = g_dst[i];
        int p = atomicAdd(&g_cursor[d], 1);
        g_col[p] = g_src[i];
    }
}

// ---------------- dense GEMM: Y[N,64] = dinv[n] * (X[N,K] @ W[K,64]) --------
__device__ __forceinline__ void ffma2(unsigned long long& acc,
                                      unsigned long long a,
                                      unsigned long long b) {
    asm("fma.rn.f32x2 %0, %1, %2, %0;" : "+l"(acc) : "l"(a), "l"(b));
}
__device__ __forceinline__ unsigned long long fmul2(unsigned long long a,
                                                    unsigned long long b) {
    unsigned long long r;
    asm("mul.rn.f32x2 %0, %1, %2;" : "=l"(r) : "l"(a), "l"(b));
    return r;
}

template <int K>
__global__ void __launch_bounds__(128) gemm64_kernel(
    const float* __restrict__ X, const float* __restrict__ W,
    float* __restrict__ Y, int N) {
    constexpr int KP = K + 4;
    extern __shared__ __align__(16) float smem[];
    float* sW = smem;            // [K][64]
    float* sX = smem + K * 64;   // [64][KP]

    int t = threadIdx.x;
    int node0 = blockIdx.x * 64;

    for (int i = t; i < K * 16; i += 128)
        ((float4*)sW)[i] = ((const float4*)W)[i];

    constexpr int RQ = K / 4;
    for (int i = t; i < 64 * RQ; i += 128) {
        int r = i / RQ, c = i % RQ;
        float4 v = make_float4(0.f, 0.f, 0.f, 0.f);
        if (node0 + r < N) v = *(const float4*)&X[(size_t)(node0 + r) * K + 4 * c];
        *(float4*)&sX[r * KP + 4 * c] = v;
    }
    __syncthreads();

    int tx = t & 7;
    int ty = t >> 3;
    unsigned long long acc[4][4];
#pragma unroll
    for (int i = 0; i < 4; i++)
#pragma unroll
        for (int j = 0; j < 4; j++) acc[i][j] = 0ull;

#pragma unroll 4
    for (int k = 0; k < K; k++) {
        ulonglong2 w0 = *(const ulonglong2*)&sW[k * 64 + 8 * tx];
        ulonglong2 w1 = *(const ulonglong2*)&sW[k * 64 + 8 * tx + 4];
#pragma unroll
        for (int i = 0; i < 4; i++) {
            float xv = sX[(4 * ty + i) * KP + k];
            unsigned long long xx;
            asm("mov.b64 %0, {%1, %1};" : "=l"(xx) : "f"(xv));
            ffma2(acc[i][0], w0.x, xx);
            ffma2(acc[i][1], w0.y, xx);
            ffma2(acc[i][2], w1.x, xx);
            ffma2(acc[i][3], w1.y, xx);
        }
    }

#pragma unroll
    for (int i = 0; i < 4; i++) {
        int node = node0 + 4 * ty + i;
        if (node < N) {
            float wd = g_dinv[node];
            unsigned long long ww;
            asm("mov.b64 %0, {%1, %1};" : "=l"(ww) : "f"(wd));
            *(ulonglong2*)&Y[(size_t)node * 64 + 8 * tx] =
                make_ulonglong2(fmul2(acc[i][0], ww), fmul2(acc[i][1], ww));
            *(ulonglong2*)&Y[(size_t)node * 64 + 8 * tx + 4] =
                make_ulonglong2(fmul2(acc[i][2], ww), fmul2(acc[i][3], ww));
        }
    }
}

// ---------------- sparse aggregation: warp per dst node ----------------------
// H is pre-scaled (h' = dinv*h). out[d] = dinv[d]*(sum h'[src] + h'[d]) + b.
__global__ void __launch_bounds__(256) agg_kernel(
    const float* __restrict__ H, const float* __restrict__ bias,
    float* __restrict__ OUT, int N, int do_relu) {
    int gw = (blockIdx.x * blockDim.x + threadIdx.x) >> 5;
    if (gw >= N) return;
    int lane = threadIdx.x & 31;

    int rs = g_rowptr[gw], re = g_rowptr[gw + 1];
    float ax = 0.f, ay = 0.f;

    int base = rs;
    for (; base + 32 <= re; base += 32) {
        int sidx = g_col[base + lane];
#pragma unroll 8
        for (int i = 0; i < 32; i++) {
            int src = __shfl_sync(0xffffffffu, sidx, i);
            float2 hv = *(const float2*)&H[(size_t)src * 64 + 2 * lane];
            ax += hv.x;
            ay += hv.y;
        }
    }
    int rem = re - base;
    if (rem > 0) {
        int sidx = (lane < rem) ? g_col[base + lane] : 0;
        for (int i = 0; i < rem; i++) {
            int src = __shfl_sync(0xffffffffu, sidx, i);
            float2 hv = *(const float2*)&H[(size_t)src * 64 + 2 * lane];
            ax += hv.x;
            ay += hv.y;
        }
    }

    float wd = g_dinv[gw];
    float2 hs = *(const float2*)&H[(size_t)gw * 64 + 2 * lane];
    float2 bv = *(const float2*)&bias[2 * lane];
    float ox = fmaf(wd, ax + hs.x, bv.x);
    float oy = fmaf(wd, ay + hs.y, bv.y);
    if (do_relu) {
        ox = fmaxf(ox, 0.f);
        oy = fmaxf(oy, 0.f);
    }
    float2 o;
    o.x = ox;
    o.y = oy;
    *(float2*)&OUT[(size_t)gw * 64 + 2 * lane] = o;
}

// ---------------- launch ------------------------------------------------------
extern "C" void kernel_launch(void* const* d_in, const int* in_sizes, int n_in,
                              void* d_out, int out_size) {
    const float* x   = (const float*)d_in[0];
    const void*  ei  = d_in[1];
    const float* W1  = (const float*)d_in[2];
    const float* b1  = (const float*)d_in[3];
    const float* W2  = (const float*)d_in[4];
    const float* b2  = (const float*)d_in[5];
    float*       out = (float*)d_out;

    int N = in_sizes[0] / 128;   // 100000
    int E = in_sizes[1] / 2;     // 3200000
    int nb = (N + 1023) / 1024;  // 98

    void *pA = nullptr, *pB = nullptr;
    cudaGetSymbolAddress(&pA, g_bufA);
    cudaGetSymbolAddress(&pB, g_bufB);
    float* bufA = (float*)pA;
    float* bufB = (float*)pB;

    int smem1 = (128 * 64 + 64 * (128 + 4)) * 4;
    int smem2 = (64 * 64 + 64 * (64 + 4)) * 4;
    cudaFuncSetAttribute(gemm64_kernel<128>,
                         cudaFuncAttributeMaxDynamicSharedMemorySize, smem1);
    cudaFuncSetAttribute(gemm64_kernel<64>,
                         cudaFuncAttributeMaxDynamicSharedMemorySize, smem2);

    // --- build CSR (dst-grouped) ---
    detect_dtype_kernel<<<1, 32>>>((const unsigned long long*)ei);
    zero_cnt_kernel<<<(N + 255) / 256, 256>>>(N);
    count_convert_kernel<<<(E + 255) / 256, 256>>>(ei, E, N);
    scan1_kernel<<<nb, 1024>>>(N);
    scan2_kernel<<<1, 128>>>(nb);
    scan3_kernel<<<(N + 255) / 256, 256>>>(N, E);
    fill_col_kernel<<<(E + 255) / 256, 256>>>(E);

    // --- layer 1: t = dinv*(x@W1) ; h = relu(dinv_d*(sum t) + b1) ---
    gemm64_kernel<128><<<(N + 63) / 64, 128, smem1>>>(x, W1, bufA, N);
    agg_kernel<<<(N + 7) / 8, 256>>>(bufA, b1, bufB, N, 1);

    // --- layer 2 ---
    gemm64_kernel<64><<<(N + 63) / 64, 128, smem2>>>(bufB, W2, bufA, N);
    agg_kernel<<<(N + 7) / 8, 256>>>(bufA, b2, out, N, 0);
}

// round 4
// speedup vs baseline: 1.4938x; 1.0020x over previous
#include <cuda_runtime.h>
#include <cuda_fp16.h>

#define MAX_NODES 100000
#define MAX_EDGES 3200000

// ---------------- scratch (device globals; no allocation allowed) ------------
__device__ int    g_is32;
__device__ int    g_cnt[MAX_NODES];
__device__ int    g_rowptr[MAX_NODES + 1];
__device__ int    g_cursor[MAX_NODES];
__device__ float  g_dinv[MAX_NODES];
__device__ int    g_src[MAX_EDGES];
__device__ int    g_dst[MAX_EDGES];
__device__ int    g_col[MAX_EDGES];
__device__ int    g_bsum[128];
__device__ int    g_boff[128];
__device__ __half g_bufH[(size_t)MAX_NODES * 64];  // fp16 pre-scaled GEMM out
__device__ float  g_bufB[(size_t)MAX_NODES * 64];  // fp32 layer-1 activations

// ---------------- dtype detection -------------------------------------------
// Reference asks for int64 edge_index, but JAX x64-off silently yields int32.
__global__ void detect_dtype_kernel(const unsigned long long* __restrict__ ei) {
    if (threadIdx.x == 0 && blockIdx.x == 0) {
        int is32 = 0;
        for (int i = 0; i < 64; i++)
            if (ei[i] >> 32) is32 = 1;
        g_is32 = is32;
    }
}

__global__ void zero_cnt_kernel(int n) {
    int i = blockIdx.x * blockDim.x + threadIdx.x;
    if (i < n) g_cnt[i] = 0;
}

__global__ void count_convert_kernel(const void* __restrict__ eiv, int E, int N) {
    int i = blockIdx.x * blockDim.x + threadIdx.x;
    if (i >= E) return;
    int s, d;
    if (g_is32) {
        const int* e = (const int*)eiv;
        s = e[i];
        d = e[E + i];
    } else {
        const long long* e = (const long long*)eiv;
        s = (int)e[i];
        d = (int)e[E + i];
    }
    if ((unsigned)s >= (unsigned)N) s = 0;
    if ((unsigned)d >= (unsigned)N) d = 0;
    g_src[i] = s;
    g_dst[i] = d;
    atomicAdd(&g_cnt[d], 1);
}

// ---------------- hierarchical exclusive scan of g_cnt ----------------------
__global__ void __launch_bounds__(1024) scan1_kernel(int N) {
    __shared__ int wsum[32];
    int t = threadIdx.x;
    int lane = t & 31, wid = t >> 5;
    int idx = blockIdx.x * 1024 + t;
    int v = (idx < N) ? g_cnt[idx] : 0;

    int x = v;
#pragma unroll
    for (int off = 1; off < 32; off <<= 1) {
        int y = __shfl_up_sync(0xffffffffu, x, off);
        if (lane >= off) x += y;
    }
    if (lane == 31) wsum[wid] = x;
    __syncthreads();
    if (wid == 0) {
        int w = wsum[lane];
#pragma unroll
        for (int off = 1; off < 32; off <<= 1) {
            int y = __shfl_up_sync(0xffffffffu, w, off);
            if (lane >= off) w += y;
        }
        wsum[lane] = w;
    }
    __syncthreads();
    int base = (wid > 0) ? wsum[wid - 1] : 0;
    int incl = x + base;
    if (idx < N) g_rowptr[idx] = incl - v;
    if (t == 1023) g_bsum[blockIdx.x] = incl;
}

__global__ void __launch_bounds__(128) scan2_kernel(int nb) {
    __shared__ int wsum[4];
    int t = threadIdx.x;
    int lane = t & 31, wid = t >> 5;
    int v = (t < nb) ? g_bsum[t] : 0;
    int x = v;
#pragma unroll
    for (int off = 1; off < 32; off <<= 1) {
        int y = __shfl_up_sync(0xffffffffu, x, off);
        if (lane >= off) x += y;
    }
    if (lane == 31) wsum[wid] = x;
    __syncthreads();
    int add = 0;
    for (int w = 0; w < wid; w++) add += wsum[w];
    if (t < nb) g_boff[t] = x + add - v;
}

__global__ void scan3_kernel(int N, int E) {
    int idx = blockIdx.x * blockDim.x + threadIdx.x;
    if (idx < N) {
        int excl = g_rowptr[idx] + g_boff[idx >> 10];
        g_rowptr[idx] = excl;
        g_cursor[idx] = excl;
        g_dinv[idx]   = rsqrtf((float)(g_cnt[idx] + 1));
    }
    if (idx == 0) g_rowptr[N] = E;
}

__global__ void fill_col_kernel(int E) {
    int i = blockIdx.x * blockDim.x + threadIdx.x;
    if (i < E) {
        int d = g_dst[i];
        int p = atomicAdd(&g_cursor[d], 1);
        g_col[p] = g_src[i];
    }
}

// ---------------- dense GEMM: Hh[N,64] = fp16(dinv[n] * (X @ W)) -------------
__device__ __forceinline__ void ffma2(unsigned long long& acc,
                                      unsigned long long a,
                                      unsigned long long b) {
    asm("fma.rn.f32x2 %0, %1, %2, %0;" : "+l"(acc) : "l"(a), "l"(b));
}

template <int K>
__global__ void __launch_bounds__(128) gemm64_kernel(
    const float* __restrict__ X, const float* __restrict__ W,
    __half* __restrict__ Y, int N) {
    constexpr int KP = K + 4;
    extern __shared__ __align__(16) float smem[];
    float* sW = smem;            // [K][64]
    float* sX = smem + K * 64;   // [64][KP]

    int t = threadIdx.x;
    int node0 = blockIdx.x * 64;

    for (int i = t; i < K * 16; i += 128)
        ((float4*)sW)[i] = ((const float4*)W)[i];

    constexpr int RQ = K / 4;
    for (int i = t; i < 64 * RQ; i += 128) {
        int r = i / RQ, c = i % RQ;
        float4 v = make_float4(0.f, 0.f, 0.f, 0.f);
        if (node0 + r < N) v = *(const float4*)&X[(size_t)(node0 + r) * K + 4 * c];
        *(float4*)&sX[r * KP + 4 * c] = v;
    }
    __syncthreads();

    int tx = t & 7;   // 8 col-groups of 8
    int ty = t >> 3;  // 16 node-groups of 4
    unsigned long long acc[4][4];
#pragma unroll
    for (int i = 0; i < 4; i++)
#pragma unroll
        for (int j = 0; j < 4; j++) acc[i][j] = 0ull;

#pragma unroll 4
    for (int k = 0; k < K; k++) {
        ulonglong2 w0 = *(const ulonglong2*)&sW[k * 64 + 8 * tx];
        ulonglong2 w1 = *(const ulonglong2*)&sW[k * 64 + 8 * tx + 4];
#pragma unroll
        for (int i = 0; i < 4; i++) {
            float xv = sX[(4 * ty + i) * KP + k];
            unsigned long long xx;
            asm("mov.b64 %0, {%1, %1};" : "=l"(xx) : "f"(xv));
            ffma2(acc[i][0], w0.x, xx);
            ffma2(acc[i][1], w0.y, xx);
            ffma2(acc[i][2], w1.x, xx);
            ffma2(acc[i][3], w1.y, xx);
        }
    }

#pragma unroll
    for (int i = 0; i < 4; i++) {
        int node = node0 + 4 * ty + i;
        if (node < N) {
            float wd = g_dinv[node];
            uint4 pk;
            unsigned* p = (unsigned*)&pk;
#pragma unroll
            for (int j = 0; j < 4; j++) {
                float lo, hi;
                asm("mov.b64 {%0, %1}, %2;" : "=f"(lo), "=f"(hi) : "l"(acc[i][j]));
                __half2 h = __floats2half2_rn(lo * wd, hi * wd);
                p[j] = *(unsigned*)&h;
            }
            *(uint4*)&Y[(size_t)node * 64 + 8 * tx] = pk;
        }
    }
}

// ---------------- sparse aggregation: warp per dst node ----------------------
// H is fp16 pre-scaled (h' = dinv*h). out[d] = dinv[d]*(sum h'[src] + h'[d]) + b
__global__ void __launch_bounds__(256) agg_kernel(
    const __half* __restrict__ H, const float* __restrict__ bias,
    float* __restrict__ OUT, int N, int do_relu) {
    int gw = (blockIdx.x * blockDim.x + threadIdx.x) >> 5;
    if (gw >= N) return;
    int lane = threadIdx.x & 31;

    int rs = g_rowptr[gw], re = g_rowptr[gw + 1];
    float ax = 0.f, ay = 0.f;

    int base = rs;
    for (; base + 32 <= re; base += 32) {
        int sidx = g_col[base + lane];
#pragma unroll 8
        for (int i = 0; i < 32; i++) {
            int src = __shfl_sync(0xffffffffu, sidx, i);
            __half2 hv = *(const __half2*)&H[(size_t)src * 64 + 2 * lane];
            float2 f = __half22float2(hv);
            ax += f.x;
            ay += f.y;
        }
    }
    int rem = re - base;
    if (rem > 0) {
        int sidx = (lane < rem) ? g_col[base + lane] : 0;
        for (int i = 0; i < rem; i++) {
            int src = __shfl_sync(0xffffffffu, sidx, i);
            __half2 hv = *(const __half2*)&H[(size_t)src * 64 + 2 * lane];
            float2 f = __half22float2(hv);
            ax += f.x;
            ay += f.y;
        }
    }

    float wd = g_dinv[gw];
    float2 hs = __half22float2(*(const __half2*)&H[(size_t)gw * 64 + 2 * lane]);
    float2 bv = *(const float2*)&bias[2 * lane];
    float ox = fmaf(wd, ax + hs.x, bv.x);
    float oy = fmaf(wd, ay + hs.y, bv.y);
    if (do_relu) {
        ox = fmaxf(ox, 0.f);
        oy = fmaxf(oy, 0.f);
    }
    float2 o;
    o.x = ox;
    o.y = oy;
    *(float2*)&OUT[(size_t)gw * 64 + 2 * lane] = o;
}

// ---------------- launch ------------------------------------------------------
extern "C" void kernel_launch(void* const* d_in, const int* in_sizes, int n_in,
                              void* d_out, int out_size) {
    const float* x   = (const float*)d_in[0];
    const void*  ei  = d_in[1];
    const float* W1  = (const float*)d_in[2];
    const float* b1  = (const float*)d_in[3];
    const float* W2  = (const float*)d_in[4];
    const float* b2  = (const float*)d_in[5];
    float*       out = (float*)d_out;

    int N = in_sizes[0] / 128;   // 100000
    int E = in_sizes[1] / 2;     // 3200000
    int nb = (N + 1023) / 1024;  // 98

    void *pH = nullptr, *pB = nullptr;
    cudaGetSymbolAddress(&pH, g_bufH);
    cudaGetSymbolAddress(&pB, g_bufB);
    __half* bufH = (__half*)pH;
    float*  bufB = (float*)pB;

    int smem1 = (128 * 64 + 64 * (128 + 4)) * 4;
    int smem2 = (64 * 64 + 64 * (64 + 4)) * 4;
    cudaFuncSetAttribute(gemm64_kernel<128>,
                         cudaFuncAttributeMaxDynamicSharedMemorySize, smem1);
    cudaFuncSetAttribute(gemm64_kernel<64>,
                         cudaFuncAttributeMaxDynamicSharedMemorySize, smem2);

    // --- build CSR (dst-grouped) ---
    detect_dtype_kernel<<<1, 32>>>((const unsigned long long*)ei);
    zero_cnt_kernel<<<(N + 255) / 256, 256>>>(N);
    count_convert_kernel<<<(E + 255) / 256, 256>>>(ei, E, N);
    scan1_kernel<<<nb, 1024>>>(N);
    scan2_kernel<<<1, 128>>>(nb);
    scan3_kernel<<<(N + 255) / 256, 256>>>(N, E);
    fill_col_kernel<<<(E + 255) / 256, 256>>>(E);

    // --- layer 1: Hh = fp16(dinv*(x@W1)) ; h = relu(dinv_d*(sum Hh) + b1) ---
    gemm64_kernel<128><<<(N + 63) / 64, 128, smem1>>>(x, W1, bufH, N);
    agg_kernel<<<(N + 7) / 8, 256>>>(bufH, b1, bufB, N, 1);

    // --- layer 2 ---
    gemm64_kernel<64><<<(N + 63) / 64, 128, smem2>>>(bufB, W2, bufH, N);
    agg_kernel<<<(N + 7) / 8, 256>>>(bufH, b2, out, N, 0);
}

// round 5
// speedup vs baseline: 2.2858x; 1.5302x over previous
#include <cuda_runtime.h>
#include <cuda_fp16.h>

#define MAX_NODES 100000
#define MAX_EDGES 3200000

// ---------------- scratch (device globals; no allocation allowed) ------------
__device__ int    g_is32;
__device__ int    g_cnt[MAX_NODES];
__device__ int    g_rowptr[MAX_NODES + 1];
__device__ int    g_cursor[MAX_NODES];
__device__ float  g_dinv[MAX_NODES];
__device__ int    g_col[MAX_EDGES];
__device__ int    g_bsum[128];
__device__ int    g_boff[128];
__device__ __align__(256) __half g_X16[(size_t)MAX_NODES * 128];  // fp16 input
__device__ __align__(256) __half g_W16[128 * 64 + 64 * 64];       // fp16 W1|W2
__device__ __align__(256) __half g_bufH[(size_t)MAX_NODES * 64];  // gemm out (dinv-scaled)
__device__ __align__(256) __half g_bufA[(size_t)MAX_NODES * 64];  // layer-1 activations

// ---------------- dtype detection (parallel) ---------------------------------
// Reference asks int64 edge_index; JAX x64-off silently yields int32.
__global__ void detect_dtype_kernel(const unsigned long long* __restrict__ ei) {
    __shared__ int f;
    if (threadIdx.x == 0) f = 0;
    __syncthreads();
    if (threadIdx.x < 64 && (ei[threadIdx.x] >> 32)) f = 1;
    __syncthreads();
    if (threadIdx.x == 0) g_is32 = f;
}

__global__ void zero_cnt_kernel(int n) {
    int i = blockIdx.x * blockDim.x + threadIdx.x;
    if (i < n) g_cnt[i] = 0;
}

// Count in-degree: read ONLY the dst half of the edge list (no staging).
__global__ void count_kernel(const void* __restrict__ eiv, int E, int N) {
    int i = blockIdx.x * blockDim.x + threadIdx.x;
    if (i >= E) return;
    int d;
    if (g_is32) d = ((const int*)eiv)[E + i];
    else        d = (int)((const long long*)eiv)[E + i];
    if ((unsigned)d >= (unsigned)N) d = 0;
    atomicAdd(&g_cnt[d], 1);
}

// ---------------- hierarchical exclusive scan of g_cnt ----------------------
__global__ void __launch_bounds__(1024) scan1_kernel(int N) {
    __shared__ int wsum[32];
    int t = threadIdx.x, lane = t & 31, wid = t >> 5;
    int idx = blockIdx.x * 1024 + t;
    int v = (idx < N) ? g_cnt[idx] : 0;
    int x = v;
#pragma unroll
    for (int off = 1; off < 32; off <<= 1) {
        int y = __shfl_up_sync(0xffffffffu, x, off);
        if (lane >= off) x += y;
    }
    if (lane == 31) wsum[wid] = x;
    __syncthreads();
    if (wid == 0) {
        int w = wsum[lane];
#pragma unroll
        for (int off = 1; off < 32; off <<= 1) {
            int y = __shfl_up_sync(0xffffffffu, w, off);
            if (lane >= off) w += y;
        }
        wsum[lane] = w;
    }
    __syncthreads();
    int base = (wid > 0) ? wsum[wid - 1] : 0;
    int incl = x + base;
    if (idx < N) g_rowptr[idx] = incl - v;
    if (t == 1023) g_bsum[blockIdx.x] = incl;
}

__global__ void __launch_bounds__(128) scan2_kernel(int nb) {
    __shared__ int wsum[4];
    int t = threadIdx.x, lane = t & 31, wid = t >> 5;
    int v = (t < nb) ? g_bsum[t] : 0;
    int x = v;
#pragma unroll
    for (int off = 1; off < 32; off <<= 1) {
        int y = __shfl_up_sync(0xffffffffu, x, off);
        if (lane >= off) x += y;
    }
    if (lane == 31) wsum[wid] = x;
    __syncthreads();
    int add = 0;
    for (int w = 0; w < wid; w++) add += wsum[w];
    if (t < nb) g_boff[t] = x + add - v;
}

__global__ void scan3_kernel(int N, int E) {
    int idx = blockIdx.x * blockDim.x + threadIdx.x;
    if (idx < N) {
        int excl = g_rowptr[idx] + g_boff[idx >> 10];
        g_rowptr[idx] = excl;
        g_cursor[idx] = excl;
        g_dinv[idx]   = rsqrtf((float)(g_cnt[idx] + 1));
    }
    if (idx == 0) g_rowptr[N] = E;
}

// Fill CSR columns: read edge list directly (src+dst), no intermediates.
__global__ void fill_col_kernel(const void* __restrict__ eiv, int E, int N) {
    int i = blockIdx.x * blockDim.x + threadIdx.x;
    if (i >= E) return;
    int s, d;
    if (g_is32) {
        const int* e = (const int*)eiv;
        s = e[i]; d = e[E + i];
    } else {
        const long long* e = (const long long*)eiv;
        s = (int)e[i]; d = (int)e[E + i];
    }
    if ((unsigned)s >= (unsigned)N) s = 0;
    if ((unsigned)d >= (unsigned)N) d = 0;
    int p = atomicAdd(&g_cursor[d], 1);
    g_col[p] = s;
}

// ---------------- conversions to fp16 ----------------------------------------
__global__ void xcvt_kernel(const float* __restrict__ X, __half* __restrict__ Y,
                            long long n8) {
    long long i = (long long)(blockIdx.x * blockDim.x + threadIdx.x);
    if (i >= n8) return;
    float4 a = *(const float4*)&X[i * 8];
    float4 b = *(const float4*)&X[i * 8 + 4];
    __half2 h0 = __floats2half2_rn(a.x, a.y);
    __half2 h1 = __floats2half2_rn(a.z, a.w);
    __half2 h2 = __floats2half2_rn(b.x, b.y);
    __half2 h3 = __floats2half2_rn(b.z, b.w);
    uint4 pk = make_uint4(*(unsigned*)&h0, *(unsigned*)&h1,
                          *(unsigned*)&h2, *(unsigned*)&h3);
    *(uint4*)&Y[i * 8] = pk;
}

__global__ void wcvt_kernel(const float* __restrict__ W1,
                            const float* __restrict__ W2) {
    int i = blockIdx.x * blockDim.x + threadIdx.x;
    if (i < 128 * 64) g_W16[i] = __float2half_rn(W1[i]);
    if (i < 64 * 64)  g_W16[128 * 64 + i] = __float2half_rn(W2[i]);
}

// ---------------- tensor-core GEMM: H[N,64] = fp16(dinv * (X[N,K]@W[K,64])) --
__device__ __forceinline__ void ldsm_x4(unsigned& r0, unsigned& r1,
                                        unsigned& r2, unsigned& r3,
                                        unsigned addr) {
    asm volatile("ldmatrix.sync.aligned.m8n8.x4.shared.b16 {%0,%1,%2,%3}, [%4];"
                 : "=r"(r0), "=r"(r1), "=r"(r2), "=r"(r3) : "r"(addr));
}
__device__ __forceinline__ void ldsm_x4_t(unsigned& r0, unsigned& r1,
                                          unsigned& r2, unsigned& r3,
                                          unsigned addr) {
    asm volatile("ldmatrix.sync.aligned.m8n8.x4.trans.shared.b16 {%0,%1,%2,%3}, [%4];"
                 : "=r"(r0), "=r"(r1), "=r"(r2), "=r"(r3) : "r"(addr));
}
__device__ __forceinline__ void mma16816(float* c, unsigned a0, unsigned a1,
                                         unsigned a2, unsigned a3,
                                         unsigned b0, unsigned b1) {
    asm volatile(
        "mma.sync.aligned.m16n8k16.row.col.f32.f16.f16.f32 "
        "{%0,%1,%2,%3}, {%4,%5,%6,%7}, {%8,%9}, {%0,%1,%2,%3};"
        : "+f"(c[0]), "+f"(c[1]), "+f"(c[2]), "+f"(c[3])
        : "r"(a0), "r"(a1), "r"(a2), "r"(a3), "r"(b0), "r"(b1));
}

template <int K>
__global__ void __launch_bounds__(128) gemm_tc_kernel(
    const __half* __restrict__ X, const __half* __restrict__ W,
    __half* __restrict__ Y, int N) {
    constexpr int SA = K + 8;   // smem stride (halfs) for X tile
    constexpr int SB = 64 + 8;  // smem stride for W tile
    extern __shared__ __align__(16) __half smem[];
    __half* sA = smem;               // [64][SA]
    __half* sB = smem + 64 * SA;     // [K][SB]

    int t = threadIdx.x;
    int lane = t & 31, w = t >> 5;
    int node0 = blockIdx.x * 64;

    // stage X tile (64 x K), zero-fill OOB rows
    for (int i = t; i < 64 * (K / 8); i += 128) {
        int r = i / (K / 8), c = i % (K / 8);
        uint4 v = make_uint4(0u, 0u, 0u, 0u);
        if (node0 + r < N)
            v = *(const uint4*)&X[(size_t)(node0 + r) * K + 8 * c];
        *(uint4*)&sA[r * SA + 8 * c] = v;
    }
    // stage W tile (K x 64)
    for (int i = t; i < K * 8; i += 128) {
        int r = i / 8, c = i % 8;
        *(uint4*)&sB[r * SB + 8 * c] = *(const uint4*)&W[r * 64 + 8 * c];
    }
    __syncthreads();

    unsigned sA_u = (unsigned)__cvta_generic_to_shared(sA);
    unsigned sB_u = (unsigned)__cvta_generic_to_shared(sB);

    float acc[8][4];
#pragma unroll
    for (int i = 0; i < 8; i++)
#pragma unroll
        for (int j = 0; j < 4; j++) acc[i][j] = 0.f;

    int mi = lane >> 3, r8 = lane & 7;
    int w16 = w * 16;

#pragma unroll
    for (int kk = 0; kk < K; kk += 16) {
        unsigned a0, a1, a2, a3;
        {
            unsigned addr = sA_u +
                ((w16 + (mi & 1) * 8 + r8) * SA + kk + (mi >> 1) * 8) * 2;
            ldsm_x4(a0, a1, a2, a3, addr);
        }
#pragma unroll
        for (int p = 0; p < 4; p++) {
            unsigned b0, b1, b2, b3;
            unsigned addr = sB_u +
                ((kk + (mi & 1) * 8 + r8) * SB + p * 16 + (mi >> 1) * 8) * 2;
            ldsm_x4_t(b0, b1, b2, b3, addr);
            mma16816(acc[2 * p],     a0, a1, a2, a3, b0, b1);
            mma16816(acc[2 * p + 1], a0, a1, a2, a3, b2, b3);
        }
    }

    // epilogue: scale rows by dinv, pack fp16, store
    int g = lane >> 2, tc = lane & 3;
    int row0 = node0 + w16 + g;
    int row1 = row0 + 8;
    float d0 = (row0 < N) ? g_dinv[row0] : 0.f;
    float d1 = (row1 < N) ? g_dinv[row1] : 0.f;
#pragma unroll
    for (int p = 0; p < 8; p++) {
        int col = p * 8 + 2 * tc;
        if (row0 < N) {
            __half2 h = __floats2half2_rn(acc[p][0] * d0, acc[p][1] * d0);
            *(__half2*)&Y[(size_t)row0 * 64 + col] = h;
        }
        if (row1 < N) {
            __half2 h = __floats2half2_rn(acc[p][2] * d1, acc[p][3] * d1);
            *(__half2*)&Y[(size_t)row1 * 64 + col] = h;
        }
    }
}

// ---------------- sparse aggregation: warp per dst node, no shfl -------------
// H pre-scaled (h' = dinv*h). out[d] = dinv[d]*(sum h'[src] + h'[d]) + b
template <bool HALF_OUT>
__global__ void __launch_bounds__(256) agg_kernel(
    const __half* __restrict__ H, const float* __restrict__ bias,
    void* __restrict__ outv, int N) {
    int gw = (blockIdx.x * blockDim.x + threadIdx.x) >> 5;
    if (gw >= N) return;
    int lane = threadIdx.x & 31;

    int rs = g_rowptr[gw], re = g_rowptr[gw + 1];
    float ax = 0.f, ay = 0.f;

    int e = rs;
    for (; e + 8 <= re; e += 8) {
        int c[8];
#pragma unroll
        for (int i = 0; i < 8; i++) c[i] = __ldg(&g_col[e + i]);
#pragma unroll
        for (int i = 0; i < 8; i++) {
            float2 f = __half22float2(
                *(const __half2*)&H[(size_t)c[i] * 64 + 2 * lane]);
            ax += f.x;
            ay += f.y;
        }
    }
    for (; e < re; e++) {
        int c = __ldg(&g_col[e]);
        float2 f = __half22float2(*(const __half2*)&H[(size_t)c * 64 + 2 * lane]);
        ax += f.x;
        ay += f.y;
    }

    float wd = g_dinv[gw];
    float2 hs = __half22float2(*(const __half2*)&H[(size_t)gw * 64 + 2 * lane]);
    float2 bv = *(const float2*)&bias[2 * lane];
    float ox = fmaf(wd, ax + hs.x, bv.x);
    float oy = fmaf(wd, ay + hs.y, bv.y);
    if (HALF_OUT) {
        ox = fmaxf(ox, 0.f);
        oy = fmaxf(oy, 0.f);
        __half2 h = __floats2half2_rn(ox, oy);
        *(__half2*)&((__half*)outv)[(size_t)gw * 64 + 2 * lane] = h;
    } else {
        float2 o;
        o.x = ox;
        o.y = oy;
        *(float2*)&((float*)outv)[(size_t)gw * 64 + 2 * lane] = o;
    }
}

// ---------------- launch ------------------------------------------------------
extern "C" void kernel_launch(void* const* d_in, const int* in_sizes, int n_in,
                              void* d_out, int out_size) {
    const float* x   = (const float*)d_in[0];
    const void*  ei  = d_in[1];
    const float* W1  = (const float*)d_in[2];
    const float* b1  = (const float*)d_in[3];
    const float* W2  = (const float*)d_in[4];
    const float* b2  = (const float*)d_in[5];
    float*       out = (float*)d_out;

    int N = in_sizes[0] / 128;   // 100000
    int E = in_sizes[1] / 2;     // 3200000
    int nb = (N + 1023) / 1024;  // 98

    void *pX = nullptr, *pW = nullptr, *pH = nullptr, *pA = nullptr;
    cudaGetSymbolAddress(&pX, g_X16);
    cudaGetSymbolAddress(&pW, g_W16);
    cudaGetSymbolAddress(&pH, g_bufH);
    cudaGetSymbolAddress(&pA, g_bufA);
    __half* X16  = (__half*)pX;
    __half* W16  = (__half*)pW;
    __half* bufH = (__half*)pH;
    __half* bufA = (__half*)pA;

    int smem1 = (64 * (128 + 8) + 128 * 72) * 2;  // 35840 B
    int smem2 = (64 * (64 + 8) + 64 * 72) * 2;    // 18432 B
    cudaFuncSetAttribute(gemm_tc_kernel<128>,
                         cudaFuncAttributeMaxDynamicSharedMemorySize, smem1);
    cudaFuncSetAttribute(gemm_tc_kernel<64>,
                         cudaFuncAttributeMaxDynamicSharedMemorySize, smem2);

    // --- CSR build (dst-grouped) + conversions ---
    detect_dtype_kernel<<<1, 64>>>((const unsigned long long*)ei);
    zero_cnt_kernel<<<(N + 255) / 256, 256>>>(N);
    count_kernel<<<(E + 255) / 256, 256>>>(ei, E, N);
    scan1_kernel<<<nb, 1024>>>(N);
    scan2_kernel<<<1, 128>>>(nb);
    scan3_kernel<<<(N + 255) / 256, 256>>>(N, E);
    fill_col_kernel<<<(E + 255) / 256, 256>>>(ei, E, N);

    long long n8 = (long long)N * 128 / 8;
    xcvt_kernel<<<(unsigned)((n8 + 255) / 256), 256>>>(x, X16, n8);
    wcvt_kernel<<<32, 256>>>(W1, W2);

    // --- layer 1 ---
    gemm_tc_kernel<128><<<(N + 63) / 64, 128, smem1>>>(X16, W16, bufH, N);
    agg_kernel<true><<<(N + 7) / 8, 256>>>(bufH, b1, bufA, N);

    // --- layer 2 ---
    gemm_tc_kernel<64><<<(N + 63) / 64, 128, smem2>>>(bufA, W16 + 128 * 64, bufH, N);
    agg_kernel<false><<<(N + 7) / 8, 256>>>(bufH, b2, out, N);
}